// round 1
// baseline (speedup 1.0000x reference)
#include <cuda_runtime.h>
#include <cstdint>

#define B_ 2
#define T_ 2048
#define HID_ 2048
#define NH_ 16
#define KVH_ 4
#define HD_ 128

// Scratch (allocation-free rule: __device__ globals)
__device__ float g_q[(size_t)B_ * T_ * NH_ * HD_];    // (b,t,h,d) 32 MB
__device__ float g_k[(size_t)B_ * T_ * KVH_ * HD_];   // (b,t,kh,d) 8 MB
__device__ float g_v[(size_t)B_ * T_ * KVH_ * HD_];   // 8 MB
__device__ float g_ctx[(size_t)B_ * T_ * NH_ * HD_];  // (b,t,h,d) 32 MB

// ---------------------------------------------------------------------------
// Generic fp32 SGEMM: C(M,N) = A(M,K) @ B(K,N), all row-major.
// 128x128 block tile, BK=8, 256 threads, 8x8 per-thread microtile.
// M,N divisible by 128; K divisible by 8 (true for all our shapes).
// ---------------------------------------------------------------------------
__global__ __launch_bounds__(256) void sgemm128(const float* __restrict__ A,
                                                const float* __restrict__ Bm,
                                                float* __restrict__ C,
                                                int M, int N, int K) {
    __shared__ float As[8][128];  // A tile transposed: As[k][m]
    __shared__ float Bs[8][128];  // Bs[k][n]
    const int tid = threadIdx.x;
    const int bm = blockIdx.y, bn = blockIdx.x;
    const int ty = tid >> 4, tx = tid & 15;
    const int arow = tid >> 1, aseg = (tid & 1) * 4;
    const int brow = tid >> 5, bcol = (tid & 31) * 4;

    const float* Ap = A + (size_t)(bm * 128 + arow) * K + aseg;
    const float* Bp = Bm + (size_t)brow * N + (size_t)bn * 128 + bcol;

    float acc[8][8];
#pragma unroll
    for (int i = 0; i < 8; i++)
#pragma unroll
        for (int j = 0; j < 8; j++) acc[i][j] = 0.f;

    for (int k0 = 0; k0 < K; k0 += 8) {
        float4 av = *(const float4*)(Ap + k0);
        float4 bv = *(const float4*)(Bp + (size_t)k0 * N);
        As[aseg + 0][arow] = av.x;
        As[aseg + 1][arow] = av.y;
        As[aseg + 2][arow] = av.z;
        As[aseg + 3][arow] = av.w;
        *(float4*)&Bs[brow][bcol] = bv;
        __syncthreads();
#pragma unroll
        for (int kk = 0; kk < 8; kk++) {
            float a[8], b[8];
            *(float4*)(a)     = *(const float4*)&As[kk][ty * 8];
            *(float4*)(a + 4) = *(const float4*)&As[kk][ty * 8 + 4];
            *(float4*)(b)     = *(const float4*)&Bs[kk][tx * 8];
            *(float4*)(b + 4) = *(const float4*)&Bs[kk][tx * 8 + 4];
#pragma unroll
            for (int i = 0; i < 8; i++)
#pragma unroll
                for (int j = 0; j < 8; j++)
                    acc[i][j] = fmaf(a[i], b[j], acc[i][j]);
        }
        __syncthreads();
    }

    float* Cp = C + (size_t)(bm * 128 + ty * 8) * N + (size_t)bn * 128 + tx * 8;
#pragma unroll
    for (int i = 0; i < 8; i++) {
        *(float4*)(Cp + (size_t)i * N)     = make_float4(acc[i][0], acc[i][1], acc[i][2], acc[i][3]);
        *(float4*)(Cp + (size_t)i * N + 4) = make_float4(acc[i][4], acc[i][5], acc[i][6], acc[i][7]);
    }
}

// ---------------------------------------------------------------------------
// RoPE (in-place): x is (B*T, nheads, 128). Thread handles pair (d, d+64).
// out[d]    = x[d]*cos[t,d]    - x[d+64]*sin[t,d]
// out[d+64] = x[d+64]*cos[t,d+64] + x[d]*sin[t,d+64]
// ---------------------------------------------------------------------------
__global__ void rope_kernel(float* __restrict__ x, const float* __restrict__ cosp,
                            const float* __restrict__ sinp, int nheads) {
    int idx = blockIdx.x * blockDim.x + threadIdx.x;
    int total = B_ * T_ * nheads * 64;
    if (idx >= total) return;
    int d = idx & 63;
    int h = (idx >> 6) % nheads;
    int tok = idx / (64 * nheads);
    int t = tok & (T_ - 1);
    float* p = x + ((size_t)tok * nheads + h) * HD_;
    float c1 = cosp[t * HD_ + d],      s1 = sinp[t * HD_ + d];
    float c2 = cosp[t * HD_ + d + 64], s2 = sinp[t * HD_ + d + 64];
    float x1 = p[d], x2 = p[d + 64];
    p[d]      = fmaf(x1, c1, -x2 * s1);
    p[d + 64] = fmaf(x2, c2,  x1 * s2);
}

// ---------------------------------------------------------------------------
// Flash attention, causal, GQA. BM=BN=64, D=128, 256 threads.
// Thread grid 16x16: ty owns 4 q-rows; tx owns 4 kv-cols (score phase) and
// 8 out-cols (PV phase). Online softmax in fp32. Hard causal mask (exactly
// equivalent to the reference's -1e9 additive mask after softmax).
// smem (dynamic): Qs[64][132] Ks[64][132] Vs[64][132] Ps[64][68] = 116 KB
// ---------------------------------------------------------------------------
__global__ __launch_bounds__(256) void flash_kernel(const float* __restrict__ Q,
                                                    const float* __restrict__ K,
                                                    const float* __restrict__ V,
                                                    float* __restrict__ O) {
    extern __shared__ float smemf[];
    float* Qs = smemf;            // 64*132
    float* Ks = Qs + 64 * 132;
    float* Vs = Ks + 64 * 132;
    float* Ps = Vs + 64 * 132;    // 64*68

    const int qtile = blockIdx.x;
    const int h = blockIdx.y;
    const int b = blockIdx.z;
    const int kvh = h / (NH_ / KVH_);
    const int tid = threadIdx.x;
    const int ty = tid >> 4, tx = tid & 15;
    const int q0 = qtile * 64;
    const float scale = 0.08838834764831845f;  // 1/sqrt(128)

    // Load Q tile (pre-scaled)
    const size_t qbase = ((size_t)(b * T_ + q0) * NH_ + h) * HD_;
    for (int i = tid; i < 64 * 32; i += 256) {
        int r = i >> 5, c4 = (i & 31) << 2;
        float4 v4 = *(const float4*)&Q[qbase + (size_t)r * (NH_ * HD_) + c4];
        Qs[r * 132 + c4 + 0] = v4.x * scale;
        Qs[r * 132 + c4 + 1] = v4.y * scale;
        Qs[r * 132 + c4 + 2] = v4.z * scale;
        Qs[r * 132 + c4 + 3] = v4.w * scale;
    }

    float m[4], l[4], acco[4][8];
#pragma unroll
    for (int i = 0; i < 4; i++) { m[i] = -1e30f; l[i] = 0.f; }
#pragma unroll
    for (int i = 0; i < 4; i++)
#pragma unroll
        for (int j = 0; j < 8; j++) acco[i][j] = 0.f;

    for (int t0 = 0; t0 <= qtile; t0++) {
        const int s0 = t0 * 64;
        __syncthreads();  // previous iter done reading Ks/Vs/Ps (also covers Qs on iter 0)
        const size_t kbase = ((size_t)(b * T_ + s0) * KVH_ + kvh) * HD_;
        for (int i = tid; i < 64 * 32; i += 256) {
            int r = i >> 5, c4 = (i & 31) << 2;
            *(float4*)&Ks[r * 132 + c4] = *(const float4*)&K[kbase + (size_t)r * (KVH_ * HD_) + c4];
            *(float4*)&Vs[r * 132 + c4] = *(const float4*)&V[kbase + (size_t)r * (KVH_ * HD_) + c4];
        }
        __syncthreads();

        // S = Qs @ Ks^T (4x4 per thread)
        float s[4][4];
#pragma unroll
        for (int i = 0; i < 4; i++)
#pragma unroll
            for (int j = 0; j < 4; j++) s[i][j] = 0.f;

        for (int d = 0; d < HD_; d += 4) {
            float4 a[4], bb[4];
#pragma unroll
            for (int i = 0; i < 4; i++) a[i]  = *(const float4*)&Qs[(ty * 4 + i) * 132 + d];
#pragma unroll
            for (int j = 0; j < 4; j++) bb[j] = *(const float4*)&Ks[(tx * 4 + j) * 132 + d];
#pragma unroll
            for (int i = 0; i < 4; i++)
#pragma unroll
                for (int j = 0; j < 4; j++) {
                    s[i][j] = fmaf(a[i].x, bb[j].x, s[i][j]);
                    s[i][j] = fmaf(a[i].y, bb[j].y, s[i][j]);
                    s[i][j] = fmaf(a[i].z, bb[j].z, s[i][j]);
                    s[i][j] = fmaf(a[i].w, bb[j].w, s[i][j]);
                }
        }

        if (t0 == qtile) {  // diagonal tile: causal mask
#pragma unroll
            for (int i = 0; i < 4; i++)
#pragma unroll
                for (int j = 0; j < 4; j++)
                    if (tx * 4 + j > ty * 4 + i) s[i][j] = -1e30f;
        }

        // Online softmax
#pragma unroll
        for (int i = 0; i < 4; i++) {
            float rm = fmaxf(fmaxf(s[i][0], s[i][1]), fmaxf(s[i][2], s[i][3]));
#pragma unroll
            for (int off = 8; off; off >>= 1)
                rm = fmaxf(rm, __shfl_xor_sync(0xffffffffu, rm, off));
            float mnew = fmaxf(m[i], rm);
            float alpha = __expf(m[i] - mnew);
            float rsum = 0.f;
#pragma unroll
            for (int j = 0; j < 4; j++) {
                float p = __expf(s[i][j] - mnew);
                Ps[(ty * 4 + i) * 68 + tx * 4 + j] = p;
                rsum += p;
            }
#pragma unroll
            for (int off = 8; off; off >>= 1)
                rsum += __shfl_xor_sync(0xffffffffu, rsum, off);
            l[i] = l[i] * alpha + rsum;
            m[i] = mnew;
#pragma unroll
            for (int j = 0; j < 8; j++) acco[i][j] *= alpha;
        }
        __syncthreads();  // Ps visible to all

        // O += P @ V  (4 rows x 8 cols per thread)
        for (int ss = 0; ss < 64; ss++) {
            float a[4];
#pragma unroll
            for (int i = 0; i < 4; i++) a[i] = Ps[(ty * 4 + i) * 68 + ss];
            float vv[8];
            *(float4*)(vv)     = *(const float4*)&Vs[ss * 132 + tx * 8];
            *(float4*)(vv + 4) = *(const float4*)&Vs[ss * 132 + tx * 8 + 4];
#pragma unroll
            for (int i = 0; i < 4; i++)
#pragma unroll
                for (int j = 0; j < 8; j++)
                    acco[i][j] = fmaf(a[i], vv[j], acco[i][j]);
        }
    }

    // Normalize and write ctx (b,t,h,d)
#pragma unroll
    for (int i = 0; i < 4; i++) {
        float inv = 1.f / l[i];
        size_t row = ((size_t)(b * T_ + q0 + ty * 4 + i) * NH_ + h) * HD_ + tx * 8;
        *(float4*)&O[row]     = make_float4(acco[i][0] * inv, acco[i][1] * inv,
                                            acco[i][2] * inv, acco[i][3] * inv);
        *(float4*)&O[row + 4] = make_float4(acco[i][4] * inv, acco[i][5] * inv,
                                            acco[i][6] * inv, acco[i][7] * inv);
    }
}

// ---------------------------------------------------------------------------
// Launch
// ---------------------------------------------------------------------------
extern "C" void kernel_launch(void* const* d_in, const int* in_sizes, int n_in,
                              void* d_out, int out_size) {
    const float* hidden = (const float*)d_in[0];
    // d_in[1] = attention_mask (pure causal -1e9; implemented directly)
    const float* cosp = (const float*)d_in[2];
    const float* sinp = (const float*)d_in[3];
    const float* Wq = (const float*)d_in[4];
    const float* Wk = (const float*)d_in[5];
    const float* Wv = (const float*)d_in[6];
    const float* Wo = (const float*)d_in[7];
    float* out = (float*)d_out;

    float *q, *k, *v, *ctx;
    cudaGetSymbolAddress((void**)&q, g_q);
    cudaGetSymbolAddress((void**)&k, g_k);
    cudaGetSymbolAddress((void**)&v, g_v);
    cudaGetSymbolAddress((void**)&ctx, g_ctx);

    const int M = B_ * T_;  // 4096

    // QKV projections
    sgemm128<<<dim3((NH_ * HD_) / 128, M / 128), 256>>>(hidden, Wq, q, M, NH_ * HD_, HID_);
    sgemm128<<<dim3((KVH_ * HD_) / 128, M / 128), 256>>>(hidden, Wk, k, M, KVH_ * HD_, HID_);
    sgemm128<<<dim3((KVH_ * HD_) / 128, M / 128), 256>>>(hidden, Wv, v, M, KVH_ * HD_, HID_);

    // RoPE
    rope_kernel<<<(B_ * T_ * NH_ * 64 + 255) / 256, 256>>>(q, cosp, sinp, NH_);
    rope_kernel<<<(B_ * T_ * KVH_ * 64 + 255) / 256, 256>>>(k, cosp, sinp, KVH_);

    // Flash attention
    size_t shmem = (size_t)(3 * 64 * 132 + 64 * 68) * sizeof(float);  // 118784 B
    cudaFuncSetAttribute(flash_kernel, cudaFuncAttributeMaxDynamicSharedMemorySize, (int)shmem);
    flash_kernel<<<dim3(T_ / 64, NH_, B_), 256, shmem>>>(q, k, v, ctx);

    // Output projection
    sgemm128<<<dim3(HID_ / 128, M / 128), 256>>>(ctx, Wo, out, M, HID_, HID_);
}

// round 3
// speedup vs baseline: 1.5277x; 1.5277x over previous
#include <cuda_runtime.h>
#include <cuda_bf16.h>
#include <cstdint>

#define B_ 2
#define T_ 2048
#define HID_ 2048
#define NH_ 16
#define KVH_ 4
#define HD_ 128

typedef __nv_bfloat16 bf16;

// fp32 scratch
__device__ float g_q[(size_t)B_ * T_ * NH_ * HD_];
__device__ float g_k[(size_t)B_ * T_ * KVH_ * HD_];
__device__ float g_v[(size_t)B_ * T_ * KVH_ * HD_];
__device__ float g_ctx[(size_t)B_ * T_ * NH_ * HD_];
// bf16 split scratch, K tripled: A pattern [hi,hi,lo], B pattern [hi,lo,hi]
#define K3 (3 * HID_)   // 6144
__device__ bf16 g_hid_i[(size_t)4096 * K3];
__device__ bf16 g_ctx_i[(size_t)4096 * K3];
__device__ bf16 g_wq_i[(size_t)K3 * 2048];
__device__ bf16 g_wk_i[(size_t)K3 * 512];
__device__ bf16 g_wv_i[(size_t)K3 * 512];
__device__ bf16 g_wo_i[(size_t)K3 * 2048];

// ---------------------------------------------------------------------------
// Split fp32 -> bf16 triple, A-side (row-major MxK -> Mx3K): [hi, hi, lo]
// ---------------------------------------------------------------------------
__global__ void split_rows3(const float* __restrict__ in, bf16* __restrict__ out,
                            int total) {
    int i = blockIdx.x * blockDim.x + threadIdx.x;
    if (i >= total) return;
    float x = in[i];
    bf16 h = __float2bfloat16(x);
    float lo = x - __bfloat162float(h);
    out[3 * i]     = h;
    out[3 * i + 1] = h;
    out[3 * i + 2] = __float2bfloat16(lo);
}

// B-side (row-major KxN -> 3KxN): row 3k = hi, 3k+1 = lo, 3k+2 = hi.
// Dot over the tripled K: xh*yh + xh*yl + xl*yh  (xl*yl dropped, ~2^-18)
__global__ void split_cols3(const float* __restrict__ in, bf16* __restrict__ out,
                            int K, int N) {
    int i = blockIdx.x * blockDim.x + threadIdx.x;
    if (i >= K * N) return;
    int k = i / N, n = i - k * N;
    float x = in[i];
    bf16 h = __float2bfloat16(x);
    float lo = x - __bfloat162float(h);
    out[(size_t)(3 * k) * N + n]     = h;
    out[(size_t)(3 * k + 1) * N + n] = __float2bfloat16(lo);
    out[(size_t)(3 * k + 2) * N + n] = h;
}

// ---------------------------------------------------------------------------
// bf16 GEMM: C(M,N) fp32 = A(M,K) @ B(K,N), A,B bf16 row-major.
// 128x128x64 tile, 3-stage cp.async pipeline, mma.sync.m16n8k16, 256 threads.
// ---------------------------------------------------------------------------
#define GBM 128
#define GBN 128
#define GBK 64
#define GSTAGES 3
#define A_STAGE_BYTES (GBM * GBK * 2)
#define B_STAGE_BYTES (GBK * GBN * 2)

__device__ __forceinline__ void cp16(uint32_t s, const void* g) {
    asm volatile("cp.async.cg.shared.global [%0], [%1], 16;\n" :: "r"(s), "l"(g));
}
__device__ __forceinline__ void cp_commit() {
    asm volatile("cp.async.commit_group;\n" ::);
}
__device__ __forceinline__ void mma16816(float* c, const uint32_t* a, const uint32_t* b) {
    asm volatile(
        "mma.sync.aligned.m16n8k16.row.col.f32.bf16.bf16.f32 "
        "{%0,%1,%2,%3}, {%4,%5,%6,%7}, {%8,%9}, {%0,%1,%2,%3};\n"
        : "+f"(c[0]), "+f"(c[1]), "+f"(c[2]), "+f"(c[3])
        : "r"(a[0]), "r"(a[1]), "r"(a[2]), "r"(a[3]), "r"(b[0]), "r"(b[1]));
}

__global__ __launch_bounds__(256, 1) void bf16gemm(const bf16* __restrict__ A,
                                                   const bf16* __restrict__ B,
                                                   float* __restrict__ C,
                                                   int M, int N, int K) {
    extern __shared__ char sm[];
    const uint32_t smBase = (uint32_t)__cvta_generic_to_shared(sm);
    const uint32_t aBase = smBase;
    const uint32_t bBase = smBase + GSTAGES * A_STAGE_BYTES;

    const int tid = threadIdx.x;
    const int bm = blockIdx.y, bn = blockIdx.x;
    const int warp = tid >> 5, lane = tid & 31;
    const int wm = warp >> 2;
    const int wn = warp & 3;

    float acc[4][4][4];
#pragma unroll
    for (int mi = 0; mi < 4; mi++)
#pragma unroll
        for (int ni = 0; ni < 4; ni++)
#pragma unroll
            for (int e = 0; e < 4; e++) acc[mi][ni][e] = 0.f;

    const int KT = K / GBK;

    auto load_stage = [&](int sidx, int kt) {
#pragma unroll
        for (int i = 0; i < 4; i++) {
            int q = tid + i * 256;
            int r = q >> 3, c = q & 7;
            const bf16* g = A + (size_t)(bm * GBM + r) * K + kt * GBK + c * 8;
            uint32_t s = aBase + sidx * A_STAGE_BYTES + r * 128 + (((c ^ (r & 7)) & 7) << 4);
            cp16(s, g);
        }
#pragma unroll
        for (int i = 0; i < 4; i++) {
            int q = tid + i * 256;
            int r = q >> 4, c = q & 15;
            const bf16* g = B + (size_t)(kt * GBK + r) * N + bn * GBN + c * 8;
            int ch = (c & 8) | ((c ^ (r & 7)) & 7);
            uint32_t s = bBase + sidx * B_STAGE_BYTES + r * 256 + (ch << 4);
            cp16(s, g);
        }
    };

#pragma unroll
    for (int s = 0; s < GSTAGES - 1; s++) {
        load_stage(s, s);
        cp_commit();
    }
    asm volatile("cp.async.wait_group %0;\n" :: "n"(GSTAGES - 2));
    __syncthreads();

    const int a_row = wm * 64 + (lane & 15);
    const int a_col8 = (lane >> 4) * 8;
    const int b_row = (lane & 15);
    const int b_colb = wn * 32 + (lane >> 4) * 8;

    for (int kt = 0; kt < KT; kt++) {
        const int cur = kt % GSTAGES;
        if (kt + GSTAGES - 1 < KT) load_stage((kt + GSTAGES - 1) % GSTAGES, kt + GSTAGES - 1);
        cp_commit();

        const uint32_t aS = aBase + cur * A_STAGE_BYTES;
        const uint32_t bS = bBase + cur * B_STAGE_BYTES;

#pragma unroll
        for (int ks = 0; ks < GBK / 16; ks++) {
            uint32_t af[4][4];
#pragma unroll
            for (int mi = 0; mi < 4; mi++) {
                int row = a_row + mi * 16;
                int col = ks * 16 + a_col8;
                uint32_t addr = aS + row * 128 + ((((col >> 3) ^ (row & 7)) & 7) << 4);
                asm volatile("ldmatrix.sync.aligned.m8n8.x4.shared.b16 {%0,%1,%2,%3}, [%4];\n"
                             : "=r"(af[mi][0]), "=r"(af[mi][1]), "=r"(af[mi][2]), "=r"(af[mi][3])
                             : "r"(addr));
            }
            uint32_t bfr[4][2];
#pragma unroll
            for (int np = 0; np < 2; np++) {
                int row = ks * 16 + b_row;
                int col = b_colb + np * 16;
                int ch = (col >> 3);
                ch = (ch & 8) | ((ch ^ (row & 7)) & 7);
                uint32_t addr = bS + row * 256 + (ch << 4);
                asm volatile("ldmatrix.sync.aligned.m8n8.x4.trans.shared.b16 {%0,%1,%2,%3}, [%4];\n"
                             : "=r"(bfr[np * 2][0]), "=r"(bfr[np * 2][1]),
                               "=r"(bfr[np * 2 + 1][0]), "=r"(bfr[np * 2 + 1][1])
                             : "r"(addr));
            }
#pragma unroll
            for (int mi = 0; mi < 4; mi++)
#pragma unroll
                for (int ni = 0; ni < 4; ni++)
                    mma16816(acc[mi][ni], af[mi], bfr[ni]);
        }

        asm volatile("cp.async.wait_group %0;\n" :: "n"(GSTAGES - 2));
        __syncthreads();
    }

#pragma unroll
    for (int mi = 0; mi < 4; mi++) {
#pragma unroll
        for (int ni = 0; ni < 4; ni++) {
            int row = bm * GBM + wm * 64 + mi * 16 + (lane >> 2);
            int col = bn * GBN + wn * 32 + ni * 8 + (lane & 3) * 2;
            *(float2*)&C[(size_t)row * N + col] = make_float2(acc[mi][ni][0], acc[mi][ni][1]);
            *(float2*)&C[(size_t)(row + 8) * N + col] = make_float2(acc[mi][ni][2], acc[mi][ni][3]);
        }
    }
}

// ---------------------------------------------------------------------------
// RoPE (in-place)
// ---------------------------------------------------------------------------
__global__ void rope_kernel(float* __restrict__ x, const float* __restrict__ cosp,
                            const float* __restrict__ sinp, int nheads) {
    int idx = blockIdx.x * blockDim.x + threadIdx.x;
    int total = B_ * T_ * nheads * 64;
    if (idx >= total) return;
    int d = idx & 63;
    int h = (idx >> 6) % nheads;
    int tok = idx / (64 * nheads);
    int t = tok & (T_ - 1);
    float* p = x + ((size_t)tok * nheads + h) * HD_;
    float c1 = cosp[t * HD_ + d],      s1 = sinp[t * HD_ + d];
    float c2 = cosp[t * HD_ + d + 64], s2 = sinp[t * HD_ + d + 64];
    float x1 = p[d], x2 = p[d + 64];
    p[d]      = fmaf(x1, c1, -x2 * s1);
    p[d + 64] = fmaf(x2, c2,  x1 * s2);
}

// ---------------------------------------------------------------------------
// Flash attention (fp32), unchanged.
// ---------------------------------------------------------------------------
__global__ __launch_bounds__(256) void flash_kernel(const float* __restrict__ Q,
                                                    const float* __restrict__ K,
                                                    const float* __restrict__ V,
                                                    float* __restrict__ O) {
    extern __shared__ float smemf[];
    float* Qs = smemf;
    float* Ks = Qs + 64 * 132;
    float* Vs = Ks + 64 * 132;
    float* Ps = Vs + 64 * 132;

    const int qtile = blockIdx.x;
    const int h = blockIdx.y;
    const int b = blockIdx.z;
    const int kvh = h / (NH_ / KVH_);
    const int tid = threadIdx.x;
    const int ty = tid >> 4, tx = tid & 15;
    const int q0 = qtile * 64;
    const float scale = 0.08838834764831845f;

    const size_t qbase = ((size_t)(b * T_ + q0) * NH_ + h) * HD_;
    for (int i = tid; i < 64 * 32; i += 256) {
        int r = i >> 5, c4 = (i & 31) << 2;
        float4 v4 = *(const float4*)&Q[qbase + (size_t)r * (NH_ * HD_) + c4];
        Qs[r * 132 + c4 + 0] = v4.x * scale;
        Qs[r * 132 + c4 + 1] = v4.y * scale;
        Qs[r * 132 + c4 + 2] = v4.z * scale;
        Qs[r * 132 + c4 + 3] = v4.w * scale;
    }

    float m[4], l[4], acco[4][8];
#pragma unroll
    for (int i = 0; i < 4; i++) { m[i] = -1e30f; l[i] = 0.f; }
#pragma unroll
    for (int i = 0; i < 4; i++)
#pragma unroll
        for (int j = 0; j < 8; j++) acco[i][j] = 0.f;

    for (int t0 = 0; t0 <= qtile; t0++) {
        const int s0 = t0 * 64;
        __syncthreads();
        const size_t kbase = ((size_t)(b * T_ + s0) * KVH_ + kvh) * HD_;
        for (int i = tid; i < 64 * 32; i += 256) {
            int r = i >> 5, c4 = (i & 31) << 2;
            *(float4*)&Ks[r * 132 + c4] = *(const float4*)&K[kbase + (size_t)r * (KVH_ * HD_) + c4];
            *(float4*)&Vs[r * 132 + c4] = *(const float4*)&V[kbase + (size_t)r * (KVH_ * HD_) + c4];
        }
        __syncthreads();

        float s[4][4];
#pragma unroll
        for (int i = 0; i < 4; i++)
#pragma unroll
            for (int j = 0; j < 4; j++) s[i][j] = 0.f;

        for (int d = 0; d < HD_; d += 4) {
            float4 a[4], bb[4];
#pragma unroll
            for (int i = 0; i < 4; i++) a[i]  = *(const float4*)&Qs[(ty * 4 + i) * 132 + d];
#pragma unroll
            for (int j = 0; j < 4; j++) bb[j] = *(const float4*)&Ks[(tx * 4 + j) * 132 + d];
#pragma unroll
            for (int i = 0; i < 4; i++)
#pragma unroll
                for (int j = 0; j < 4; j++) {
                    s[i][j] = fmaf(a[i].x, bb[j].x, s[i][j]);
                    s[i][j] = fmaf(a[i].y, bb[j].y, s[i][j]);
                    s[i][j] = fmaf(a[i].z, bb[j].z, s[i][j]);
                    s[i][j] = fmaf(a[i].w, bb[j].w, s[i][j]);
                }
        }

        if (t0 == qtile) {
#pragma unroll
            for (int i = 0; i < 4; i++)
#pragma unroll
                for (int j = 0; j < 4; j++)
                    if (tx * 4 + j > ty * 4 + i) s[i][j] = -1e30f;
        }

#pragma unroll
        for (int i = 0; i < 4; i++) {
            float rm = fmaxf(fmaxf(s[i][0], s[i][1]), fmaxf(s[i][2], s[i][3]));
#pragma unroll
            for (int off = 8; off; off >>= 1)
                rm = fmaxf(rm, __shfl_xor_sync(0xffffffffu, rm, off));
            float mnew = fmaxf(m[i], rm);
            float alpha = __expf(m[i] - mnew);
            float rsum = 0.f;
#pragma unroll
            for (int j = 0; j < 4; j++) {
                float p = __expf(s[i][j] - mnew);
                Ps[(ty * 4 + i) * 68 + tx * 4 + j] = p;
                rsum += p;
            }
#pragma unroll
            for (int off = 8; off; off >>= 1)
                rsum += __shfl_xor_sync(0xffffffffu, rsum, off);
            l[i] = l[i] * alpha + rsum;
            m[i] = mnew;
#pragma unroll
            for (int j = 0; j < 8; j++) acco[i][j] *= alpha;
        }
        __syncthreads();

        for (int ss = 0; ss < 64; ss++) {
            float a[4];
#pragma unroll
            for (int i = 0; i < 4; i++) a[i] = Ps[(ty * 4 + i) * 68 + ss];
            float vv[8];
            *(float4*)(vv)     = *(const float4*)&Vs[ss * 132 + tx * 8];
            *(float4*)(vv + 4) = *(const float4*)&Vs[ss * 132 + tx * 8 + 4];
#pragma unroll
            for (int i = 0; i < 4; i++)
#pragma unroll
                for (int j = 0; j < 8; j++)
                    acco[i][j] = fmaf(a[i], vv[j], acco[i][j]);
        }
    }

#pragma unroll
    for (int i = 0; i < 4; i++) {
        float inv = 1.f / l[i];
        size_t row = ((size_t)(b * T_ + q0 + ty * 4 + i) * NH_ + h) * HD_ + tx * 8;
        *(float4*)&O[row]     = make_float4(acco[i][0] * inv, acco[i][1] * inv,
                                            acco[i][2] * inv, acco[i][3] * inv);
        *(float4*)&O[row + 4] = make_float4(acco[i][4] * inv, acco[i][5] * inv,
                                            acco[i][6] * inv, acco[i][7] * inv);
    }
}

// ---------------------------------------------------------------------------
// Launch
// ---------------------------------------------------------------------------
extern "C" void kernel_launch(void* const* d_in, const int* in_sizes, int n_in,
                              void* d_out, int out_size) {
    const float* hidden = (const float*)d_in[0];
    const float* cosp = (const float*)d_in[2];
    const float* sinp = (const float*)d_in[3];
    const float* Wq = (const float*)d_in[4];
    const float* Wk = (const float*)d_in[5];
    const float* Wv = (const float*)d_in[6];
    const float* Wo = (const float*)d_in[7];
    float* out = (float*)d_out;

    float *q, *k, *v, *ctx;
    bf16 *hid_i, *ctx_i, *wq_i, *wk_i, *wv_i, *wo_i;
    cudaGetSymbolAddress((void**)&q, g_q);
    cudaGetSymbolAddress((void**)&k, g_k);
    cudaGetSymbolAddress((void**)&v, g_v);
    cudaGetSymbolAddress((void**)&ctx, g_ctx);
    cudaGetSymbolAddress((void**)&hid_i, g_hid_i);
    cudaGetSymbolAddress((void**)&ctx_i, g_ctx_i);
    cudaGetSymbolAddress((void**)&wq_i, g_wq_i);
    cudaGetSymbolAddress((void**)&wk_i, g_wk_i);
    cudaGetSymbolAddress((void**)&wv_i, g_wv_i);
    cudaGetSymbolAddress((void**)&wo_i, g_wo_i);

    const int M = B_ * T_;      // 4096

    cudaFuncSetAttribute(bf16gemm, cudaFuncAttributeMaxDynamicSharedMemorySize,
                         GSTAGES * (A_STAGE_BYTES + B_STAGE_BYTES));
    cudaFuncSetAttribute(flash_kernel, cudaFuncAttributeMaxDynamicSharedMemorySize,
                         (int)((3 * 64 * 132 + 64 * 68) * sizeof(float)));

    // splits (triple interleave)
    split_rows3<<<(M * HID_ + 255) / 256, 256>>>(hidden, hid_i, M * HID_);
    split_cols3<<<(HID_ * 2048 + 255) / 256, 256>>>(Wq, wq_i, HID_, 2048);
    split_cols3<<<(HID_ * 512 + 255) / 256, 256>>>(Wk, wk_i, HID_, 512);
    split_cols3<<<(HID_ * 512 + 255) / 256, 256>>>(Wv, wv_i, HID_, 512);
    split_cols3<<<(HID_ * 2048 + 255) / 256, 256>>>(Wo, wo_i, HID_, 2048);

    const int gsm = GSTAGES * (A_STAGE_BYTES + B_STAGE_BYTES);  // 96 KB

    // projections (bf16 tensor-core, 3-term split precision)
    bf16gemm<<<dim3(2048 / GBN, M / GBM), 256, gsm>>>(hid_i, wq_i, q, M, 2048, K3);
    bf16gemm<<<dim3(512 / GBN, M / GBM), 256, gsm>>>(hid_i, wk_i, k, M, 512, K3);
    bf16gemm<<<dim3(512 / GBN, M / GBM), 256, gsm>>>(hid_i, wv_i, v, M, 512, K3);

    // RoPE
    rope_kernel<<<(B_ * T_ * NH_ * 64 + 255) / 256, 256>>>(q, cosp, sinp, NH_);
    rope_kernel<<<(B_ * T_ * KVH_ * 64 + 255) / 256, 256>>>(k, cosp, sinp, KVH_);

    // flash attention
    size_t shmem = (size_t)(3 * 64 * 132 + 64 * 68) * sizeof(float);
    flash_kernel<<<dim3(T_ / 64, NH_, B_), 256, shmem>>>(q, k, v, ctx);

    // output projection
    split_rows3<<<(M * HID_ + 255) / 256, 256>>>(ctx, ctx_i, M * HID_);
    bf16gemm<<<dim3(2048 / GBN, M / GBM), 256, gsm>>>(ctx_i, wo_i, out, M, 2048, K3);
}

// round 4
// speedup vs baseline: 3.6020x; 2.3577x over previous
#include <cuda_runtime.h>
#include <cuda_bf16.h>
#include <cstdint>

#define B_ 2
#define T_ 2048
#define HID_ 2048
#define NH_ 16
#define KVH_ 4
#define HD_ 128

typedef __nv_bfloat16 bf16;

// fp32 projection outputs
__device__ float g_q[(size_t)B_ * T_ * NH_ * HD_];
__device__ float g_k[(size_t)B_ * T_ * KVH_ * HD_];
__device__ float g_v[(size_t)B_ * T_ * KVH_ * HD_];
// GEMM split inputs (K tripled: A=[hi,hi,lo], B=[hi,lo,hi])
#define K3 (3 * HID_)
__device__ bf16 g_hid_i[(size_t)4096 * K3];
__device__ bf16 g_ctx_i[(size_t)4096 * K3];   // written by flash epilogue
__device__ bf16 g_wq_i[(size_t)K3 * 2048];
__device__ bf16 g_wk_i[(size_t)K3 * 512];
__device__ bf16 g_wv_i[(size_t)K3 * 512];
__device__ bf16 g_wo_i[(size_t)K3 * 2048];
// flash inputs: hi/lo bf16 pairs
__device__ bf16 g_qh[(size_t)B_ * T_ * NH_ * HD_];
__device__ bf16 g_ql[(size_t)B_ * T_ * NH_ * HD_];
__device__ bf16 g_kh[(size_t)B_ * T_ * KVH_ * HD_];
__device__ bf16 g_kl[(size_t)B_ * T_ * KVH_ * HD_];
__device__ bf16 g_vh[(size_t)B_ * T_ * KVH_ * HD_];
__device__ bf16 g_vl[(size_t)B_ * T_ * KVH_ * HD_];

// ---------------------------------------------------------------------------
// helpers
// ---------------------------------------------------------------------------
__device__ __forceinline__ void cp16(uint32_t s, const void* g) {
    asm volatile("cp.async.cg.shared.global [%0], [%1], 16;\n" :: "r"(s), "l"(g));
}
__device__ __forceinline__ void cp_commit() {
    asm volatile("cp.async.commit_group;\n" ::);
}
__device__ __forceinline__ void mma16816(float* c, const uint32_t* a, const uint32_t* b) {
    asm volatile(
        "mma.sync.aligned.m16n8k16.row.col.f32.bf16.bf16.f32 "
        "{%0,%1,%2,%3}, {%4,%5,%6,%7}, {%8,%9}, {%0,%1,%2,%3};\n"
        : "+f"(c[0]), "+f"(c[1]), "+f"(c[2]), "+f"(c[3])
        : "r"(a[0]), "r"(a[1]), "r"(a[2]), "r"(a[3]), "r"(b[0]), "r"(b[1]));
}
__device__ __forceinline__ void ldsm4(uint32_t* d, uint32_t addr) {
    asm volatile("ldmatrix.sync.aligned.m8n8.x4.shared.b16 {%0,%1,%2,%3}, [%4];\n"
                 : "=r"(d[0]), "=r"(d[1]), "=r"(d[2]), "=r"(d[3]) : "r"(addr));
}
__device__ __forceinline__ void ldsm4t(uint32_t* d, uint32_t addr) {
    asm volatile("ldmatrix.sync.aligned.m8n8.x4.trans.shared.b16 {%0,%1,%2,%3}, [%4];\n"
                 : "=r"(d[0]), "=r"(d[1]), "=r"(d[2]), "=r"(d[3]) : "r"(addr));
}
__device__ __forceinline__ float ex2(float x) {
    float r;
    asm("ex2.approx.f32 %0, %1;" : "=f"(r) : "f"(x));
    return r;
}
__device__ __forceinline__ uint32_t packbf2(float a, float b) {
    __nv_bfloat162 t = __floats2bfloat162_rn(a, b);
    return *(uint32_t*)&t;
}
__device__ __forceinline__ unsigned short bfbits(float v) {
    bf16 h = __float2bfloat16(v);
    return *(unsigned short*)&h;
}

// ---------------------------------------------------------------------------
// Splits for the projection GEMMs (unchanged from R3)
// ---------------------------------------------------------------------------
__global__ void split_rows3(const float* __restrict__ in, bf16* __restrict__ out,
                            int total) {
    int i = blockIdx.x * blockDim.x + threadIdx.x;
    if (i >= total) return;
    float x = in[i];
    bf16 h = __float2bfloat16(x);
    float lo = x - __bfloat162float(h);
    out[3 * i] = h;
    out[3 * i + 1] = h;
    out[3 * i + 2] = __float2bfloat16(lo);
}
__global__ void split_cols3(const float* __restrict__ in, bf16* __restrict__ out,
                            int K, int N) {
    int i = blockIdx.x * blockDim.x + threadIdx.x;
    if (i >= K * N) return;
    int k = i / N, n = i - k * N;
    float x = in[i];
    bf16 h = __float2bfloat16(x);
    float lo = x - __bfloat162float(h);
    out[(size_t)(3 * k) * N + n] = h;
    out[(size_t)(3 * k + 1) * N + n] = __float2bfloat16(lo);
    out[(size_t)(3 * k + 2) * N + n] = h;
}

// ---------------------------------------------------------------------------
// bf16 GEMM (unchanged from R3)
// ---------------------------------------------------------------------------
#define GBM 128
#define GBN 128
#define GBK 64
#define GSTAGES 3
#define A_STAGE_BYTES (GBM * GBK * 2)
#define B_STAGE_BYTES (GBK * GBN * 2)

__global__ __launch_bounds__(256, 1) void bf16gemm(const bf16* __restrict__ A,
                                                   const bf16* __restrict__ B,
                                                   float* __restrict__ C,
                                                   int M, int N, int K) {
    extern __shared__ char sm[];
    const uint32_t smBase = (uint32_t)__cvta_generic_to_shared(sm);
    const uint32_t aBase = smBase;
    const uint32_t bBase = smBase + GSTAGES * A_STAGE_BYTES;

    const int tid = threadIdx.x;
    const int bm = blockIdx.y, bn = blockIdx.x;
    const int warp = tid >> 5, lane = tid & 31;
    const int wm = warp >> 2;
    const int wn = warp & 3;

    float acc[4][4][4];
#pragma unroll
    for (int mi = 0; mi < 4; mi++)
#pragma unroll
        for (int ni = 0; ni < 4; ni++)
#pragma unroll
            for (int e = 0; e < 4; e++) acc[mi][ni][e] = 0.f;

    const int KT = K / GBK;

    auto load_stage = [&](int sidx, int kt) {
#pragma unroll
        for (int i = 0; i < 4; i++) {
            int q = tid + i * 256;
            int r = q >> 3, c = q & 7;
            const bf16* g = A + (size_t)(bm * GBM + r) * K + kt * GBK + c * 8;
            uint32_t s = aBase + sidx * A_STAGE_BYTES + r * 128 + (((c ^ (r & 7)) & 7) << 4);
            cp16(s, g);
        }
#pragma unroll
        for (int i = 0; i < 4; i++) {
            int q = tid + i * 256;
            int r = q >> 4, c = q & 15;
            const bf16* g = B + (size_t)(kt * GBK + r) * N + bn * GBN + c * 8;
            int ch = (c & 8) | ((c ^ (r & 7)) & 7);
            uint32_t s = bBase + sidx * B_STAGE_BYTES + r * 256 + (ch << 4);
            cp16(s, g);
        }
    };

#pragma unroll
    for (int s = 0; s < GSTAGES - 1; s++) {
        load_stage(s, s);
        cp_commit();
    }
    asm volatile("cp.async.wait_group %0;\n" :: "n"(GSTAGES - 2));
    __syncthreads();

    const int a_row = wm * 64 + (lane & 15);
    const int a_col8 = (lane >> 4) * 8;
    const int b_row = (lane & 15);
    const int b_colb = wn * 32 + (lane >> 4) * 8;

    for (int kt = 0; kt < KT; kt++) {
        const int cur = kt % GSTAGES;
        if (kt + GSTAGES - 1 < KT) load_stage((kt + GSTAGES - 1) % GSTAGES, kt + GSTAGES - 1);
        cp_commit();

        const uint32_t aS = aBase + cur * A_STAGE_BYTES;
        const uint32_t bS = bBase + cur * B_STAGE_BYTES;

#pragma unroll
        for (int ks = 0; ks < GBK / 16; ks++) {
            uint32_t af[4][4];
#pragma unroll
            for (int mi = 0; mi < 4; mi++) {
                int row = a_row + mi * 16;
                int col = ks * 16 + a_col8;
                uint32_t addr = aS + row * 128 + ((((col >> 3) ^ (row & 7)) & 7) << 4);
                ldsm4(af[mi], addr);
            }
            uint32_t bfr[4][2];
#pragma unroll
            for (int np = 0; np < 2; np++) {
                int row = ks * 16 + b_row;
                int col = b_colb + np * 16;
                int ch = (col >> 3);
                ch = (ch & 8) | ((ch ^ (row & 7)) & 7);
                uint32_t addr = bS + row * 256 + (ch << 4);
                uint32_t tmp[4];
                ldsm4t(tmp, addr);
                bfr[np * 2][0] = tmp[0]; bfr[np * 2][1] = tmp[1];
                bfr[np * 2 + 1][0] = tmp[2]; bfr[np * 2 + 1][1] = tmp[3];
            }
#pragma unroll
            for (int mi = 0; mi < 4; mi++)
#pragma unroll
                for (int ni = 0; ni < 4; ni++)
                    mma16816(acc[mi][ni], af[mi], bfr[ni]);
        }

        asm volatile("cp.async.wait_group %0;\n" :: "n"(GSTAGES - 2));
        __syncthreads();
    }

#pragma unroll
    for (int mi = 0; mi < 4; mi++) {
#pragma unroll
        for (int ni = 0; ni < 4; ni++) {
            int row = bm * GBM + wm * 64 + mi * 16 + (lane >> 2);
            int col = bn * GBN + wn * 32 + ni * 8 + (lane & 3) * 2;
            *(float2*)&C[(size_t)row * N + col] = make_float2(acc[mi][ni][0], acc[mi][ni][1]);
            *(float2*)&C[(size_t)(row + 8) * N + col] = make_float2(acc[mi][ni][2], acc[mi][ni][3]);
        }
    }
}

// ---------------------------------------------------------------------------
// RoPE + hi/lo split (scale folded into q: log2(e)/sqrt(HD))
// ---------------------------------------------------------------------------
__global__ void rope_split(const float* __restrict__ x, const float* __restrict__ cosp,
                           const float* __restrict__ sinp, bf16* __restrict__ oh,
                           bf16* __restrict__ ol, int nheads, float scale) {
    int idx = blockIdx.x * blockDim.x + threadIdx.x;
    int total = B_ * T_ * nheads * 64;
    if (idx >= total) return;
    int d = idx & 63;
    int h = (idx >> 6) % nheads;
    int tok = idx / (64 * nheads);
    int t = tok & (T_ - 1);
    size_t base = ((size_t)tok * nheads + h) * HD_;
    float c1 = cosp[t * HD_ + d], s1 = sinp[t * HD_ + d];
    float c2 = cosp[t * HD_ + d + 64], s2 = sinp[t * HD_ + d + 64];
    float x1 = x[base + d], x2 = x[base + d + 64];
    float y1 = (x1 * c1 - x2 * s1) * scale;
    float y2 = (x2 * c2 + x1 * s2) * scale;
    bf16 h1 = __float2bfloat16(y1);
    bf16 h2 = __float2bfloat16(y2);
    oh[base + d] = h1;
    oh[base + d + 64] = h2;
    ol[base + d] = __float2bfloat16(y1 - __bfloat162float(h1));
    ol[base + d + 64] = __float2bfloat16(y2 - __bfloat162float(h2));
}

__global__ void split_hl(const float* __restrict__ in, bf16* __restrict__ oh,
                         bf16* __restrict__ ol, int total) {
    int i = blockIdx.x * blockDim.x + threadIdx.x;
    if (i >= total) return;
    float x = in[i];
    bf16 h = __float2bfloat16(x);
    oh[i] = h;
    ol[i] = __float2bfloat16(x - __bfloat162float(h));
}

// ---------------------------------------------------------------------------
// Tensor-core flash attention. BM=64, BN=64, HD=128, 128 threads (4 warps).
// Warp w owns rows [16w,16w+16): softmax fully warp-local.
// S = Qh Kh^T + Qh Kl^T + Ql Kh^T ; O += Ph Vh + Ph Vl + Pl Vh.
// Epilogue writes triple-interleaved bf16 ctx_i for the O-projection GEMM.
// smem: Qh Ql Kh Kl Vh Vl, each 64x128 bf16 (16 KB) = 96 KB.
// ---------------------------------------------------------------------------
#define FTILE (64 * 128 * 2)  // 16384 bytes

__global__ __launch_bounds__(128) void flash_mma(const bf16* __restrict__ Qh,
                                                 const bf16* __restrict__ Ql,
                                                 const bf16* __restrict__ Kh,
                                                 const bf16* __restrict__ Kl,
                                                 const bf16* __restrict__ Vh,
                                                 const bf16* __restrict__ Vl,
                                                 bf16* __restrict__ ctxI) {
    extern __shared__ char sm[];
    const uint32_t smBase = (uint32_t)__cvta_generic_to_shared(sm);
    const uint32_t sQh = smBase;
    const uint32_t sQl = smBase + FTILE;
    const uint32_t sKh = smBase + 2 * FTILE;
    const uint32_t sKl = smBase + 3 * FTILE;
    const uint32_t sVh = smBase + 4 * FTILE;
    const uint32_t sVl = smBase + 5 * FTILE;

    const int tid = threadIdx.x;
    const int warp = tid >> 5, lane = tid & 31;
    const int qtile = blockIdx.x;
    const int h = blockIdx.y;
    const int b = blockIdx.z;
    const int kvh = h / (NH_ / KVH_);
    const int q0 = qtile * 64;

    // 64x128 bf16 tile loader (rows 256B, swizzled)
    auto loadTile = [&](uint32_t sbase, const bf16* g, size_t gbase, int gstride) {
#pragma unroll
        for (int i = 0; i < 8; i++) {
            int q = tid + i * 128;
            int r = q >> 4, c = q & 15;
            int ch = (c & 8) | ((c ^ (r & 7)) & 7);
            cp16(sbase + r * 256 + (ch << 4), g + gbase + (size_t)r * gstride + c * 8);
        }
    };

    const size_t qgb = ((size_t)(b * T_ + q0) * NH_ + h) * HD_;
    loadTile(sQh, Qh, qgb, NH_ * HD_);
    loadTile(sQl, Ql, qgb, NH_ * HD_);
    cp_commit();

    float oAcc[16][4];
#pragma unroll
    for (int j = 0; j < 16; j++)
#pragma unroll
        for (int e = 0; e < 4; e++) oAcc[j][e] = 0.f;
    float mrow[2] = {-1e30f, -1e30f};
    float lrow[2] = {0.f, 0.f};

    for (int t0 = 0; t0 <= qtile; t0++) {
        const int s0 = t0 * 64;
        __syncthreads();  // everyone done with previous K/V smem
        const size_t kgb = ((size_t)(b * T_ + s0) * KVH_ + kvh) * HD_;
        loadTile(sKh, Kh, kgb, KVH_ * HD_);
        loadTile(sKl, Kl, kgb, KVH_ * HD_);
        loadTile(sVh, Vh, kgb, KVH_ * HD_);
        loadTile(sVl, Vl, kgb, KVH_ * HD_);
        cp_commit();
        asm volatile("cp.async.wait_group 0;\n" ::);
        __syncthreads();

        // ---- S = Q K^T (3-product split) ----
        float sAcc[8][4];
#pragma unroll
        for (int j = 0; j < 8; j++)
#pragma unroll
            for (int e = 0; e < 4; e++) sAcc[j][e] = 0.f;

#pragma unroll
        for (int ks = 0; ks < 8; ks++) {
            // A frags from Q
            int arow = warp * 16 + (lane & 15);
            int ac = ks * 2 + (lane >> 4);
            int ach = (ac & 8) | ((ac ^ (arow & 7)) & 7);
            uint32_t ah[4], al[4];
            ldsm4(ah, sQh + arow * 256 + (ach << 4));
            ldsm4(al, sQl + arow * 256 + (ach << 4));
            // B frags from K (non-trans: K is [n][k])
            int krow_base = (lane & 7) + ((lane >> 4) & 1) * 8;
            int kc = ks * 2 + ((lane >> 3) & 1);
#pragma unroll
            for (int jp = 0; jp < 4; jp++) {
                int krow = jp * 16 + krow_base;
                int kch = (kc & 8) | ((kc ^ (krow & 7)) & 7);
                uint32_t bh4[4], bl4[4];
                ldsm4(bh4, sKh + krow * 256 + (kch << 4));
                ldsm4(bl4, sKl + krow * 256 + (kch << 4));
                mma16816(sAcc[jp * 2], ah, bh4);
                mma16816(sAcc[jp * 2], ah, bl4);
                mma16816(sAcc[jp * 2], al, bh4);
                mma16816(sAcc[jp * 2 + 1], ah, &bh4[2]);
                mma16816(sAcc[jp * 2 + 1], ah, &bl4[2]);
                mma16816(sAcc[jp * 2 + 1], al, &bh4[2]);
            }
        }

        // ---- causal mask on diagonal tile ----
        if (t0 == qtile) {
            int r0 = warp * 16 + (lane >> 2);
#pragma unroll
            for (int j = 0; j < 8; j++) {
                int cb = j * 8 + (lane & 3) * 2;
                if (cb > r0) sAcc[j][0] = -1e30f;
                if (cb + 1 > r0) sAcc[j][1] = -1e30f;
                if (cb > r0 + 8) sAcc[j][2] = -1e30f;
                if (cb + 1 > r0 + 8) sAcc[j][3] = -1e30f;
            }
        }

        // ---- online softmax (scores already scaled by log2e/sqrt(HD)) ----
        float mx0 = -1e30f, mx1 = -1e30f;
#pragma unroll
        for (int j = 0; j < 8; j++) {
            mx0 = fmaxf(mx0, fmaxf(sAcc[j][0], sAcc[j][1]));
            mx1 = fmaxf(mx1, fmaxf(sAcc[j][2], sAcc[j][3]));
        }
        mx0 = fmaxf(mx0, __shfl_xor_sync(0xffffffffu, mx0, 1));
        mx0 = fmaxf(mx0, __shfl_xor_sync(0xffffffffu, mx0, 2));
        mx1 = fmaxf(mx1, __shfl_xor_sync(0xffffffffu, mx1, 1));
        mx1 = fmaxf(mx1, __shfl_xor_sync(0xffffffffu, mx1, 2));
        float mn0 = fmaxf(mrow[0], mx0);
        float mn1 = fmaxf(mrow[1], mx1);
        float al0 = ex2(mrow[0] - mn0);
        float al1 = ex2(mrow[1] - mn1);
        mrow[0] = mn0;
        mrow[1] = mn1;
        float sum0 = 0.f, sum1 = 0.f;
#pragma unroll
        for (int j = 0; j < 8; j++) {
            sAcc[j][0] = ex2(sAcc[j][0] - mn0);
            sAcc[j][1] = ex2(sAcc[j][1] - mn0);
            sAcc[j][2] = ex2(sAcc[j][2] - mn1);
            sAcc[j][3] = ex2(sAcc[j][3] - mn1);
            sum0 += sAcc[j][0] + sAcc[j][1];
            sum1 += sAcc[j][2] + sAcc[j][3];
        }
        sum0 += __shfl_xor_sync(0xffffffffu, sum0, 1);
        sum0 += __shfl_xor_sync(0xffffffffu, sum0, 2);
        sum1 += __shfl_xor_sync(0xffffffffu, sum1, 1);
        sum1 += __shfl_xor_sync(0xffffffffu, sum1, 2);
        lrow[0] = lrow[0] * al0 + sum0;
        lrow[1] = lrow[1] * al1 + sum1;
#pragma unroll
        for (int j = 0; j < 16; j++) {
            oAcc[j][0] *= al0;
            oAcc[j][1] *= al0;
            oAcc[j][2] *= al1;
            oAcc[j][3] *= al1;
        }

        // ---- O += P V (3-product split) ----
        int vrow_b = (lane & 15);
        int vcb = (lane >> 4);
#pragma unroll
        for (int kt = 0; kt < 4; kt++) {
            // P fragments (split)
            uint32_t ph[4], pl[4];
            {
                float p0 = sAcc[2 * kt][0], p1 = sAcc[2 * kt][1];
                float p2 = sAcc[2 * kt][2], p3 = sAcc[2 * kt][3];
                float p4 = sAcc[2 * kt + 1][0], p5 = sAcc[2 * kt + 1][1];
                float p6 = sAcc[2 * kt + 1][2], p7 = sAcc[2 * kt + 1][3];
                float h0 = __bfloat162float(__float2bfloat16(p0));
                float h1 = __bfloat162float(__float2bfloat16(p1));
                float h2 = __bfloat162float(__float2bfloat16(p2));
                float h3 = __bfloat162float(__float2bfloat16(p3));
                float h4 = __bfloat162float(__float2bfloat16(p4));
                float h5 = __bfloat162float(__float2bfloat16(p5));
                float h6 = __bfloat162float(__float2bfloat16(p6));
                float h7 = __bfloat162float(__float2bfloat16(p7));
                ph[0] = packbf2(h0, h1); ph[1] = packbf2(h2, h3);
                ph[2] = packbf2(h4, h5); ph[3] = packbf2(h6, h7);
                pl[0] = packbf2(p0 - h0, p1 - h1); pl[1] = packbf2(p2 - h2, p3 - h3);
                pl[2] = packbf2(p4 - h4, p5 - h5); pl[3] = packbf2(p6 - h6, p7 - h7);
            }
            int vrow = kt * 16 + vrow_b;
#pragma unroll
            for (int jp2 = 0; jp2 < 8; jp2++) {
                int vc = jp2 * 2 + vcb;
                int vch = (vc & 8) | ((vc ^ (vrow & 7)) & 7);
                uint32_t vh4[4], vl4[4];
                ldsm4t(vh4, sVh + vrow * 256 + (vch << 4));
                ldsm4t(vl4, sVl + vrow * 256 + (vch << 4));
                mma16816(oAcc[jp2 * 2], ph, vh4);
                mma16816(oAcc[jp2 * 2], ph, vl4);
                mma16816(oAcc[jp2 * 2], pl, vh4);
                mma16816(oAcc[jp2 * 2 + 1], ph, &vh4[2]);
                mma16816(oAcc[jp2 * 2 + 1], ph, &vl4[2]);
                mma16816(oAcc[jp2 * 2 + 1], pl, &vh4[2]);
            }
        }
    }

    // ---- epilogue: normalize + triple-interleaved bf16 write ----
    float inv0 = 1.f / lrow[0];
    float inv1 = 1.f / lrow[1];
    int r0 = q0 + warp * 16 + (lane >> 2);
    size_t row0 = (size_t)(b * T_ + r0) * (3 * HID_);
    size_t row1 = row0 + (size_t)8 * (3 * HID_);
#pragma unroll
    for (int j = 0; j < 16; j++) {
        int col = h * HD_ + j * 8 + (lane & 3) * 2;
        float v0 = oAcc[j][0] * inv0, v1 = oAcc[j][1] * inv0;
        float v2 = oAcc[j][2] * inv1, v3 = oAcc[j][3] * inv1;
        unsigned short h0 = bfbits(v0), h1 = bfbits(v1);
        unsigned short h2 = bfbits(v2), h3 = bfbits(v3);
        unsigned short l0 = bfbits(v0 - __bfloat162float(__float2bfloat16(v0)));
        unsigned short l1 = bfbits(v1 - __bfloat162float(__float2bfloat16(v1)));
        unsigned short l2 = bfbits(v2 - __bfloat162float(__float2bfloat16(v2)));
        unsigned short l3 = bfbits(v3 - __bfloat162float(__float2bfloat16(v3)));
        uint32_t* p0 = (uint32_t*)(ctxI + row0 + 3 * col);
        p0[0] = (uint32_t)h0 | ((uint32_t)h0 << 16);
        p0[1] = (uint32_t)l0 | ((uint32_t)h1 << 16);
        p0[2] = (uint32_t)h1 | ((uint32_t)l1 << 16);
        uint32_t* p1 = (uint32_t*)(ctxI + row1 + 3 * col);
        p1[0] = (uint32_t)h2 | ((uint32_t)h2 << 16);
        p1[1] = (uint32_t)l2 | ((uint32_t)h3 << 16);
        p1[2] = (uint32_t)h3 | ((uint32_t)l3 << 16);
    }
}

// ---------------------------------------------------------------------------
// Launch
// ---------------------------------------------------------------------------
extern "C" void kernel_launch(void* const* d_in, const int* in_sizes, int n_in,
                              void* d_out, int out_size) {
    const float* hidden = (const float*)d_in[0];
    const float* cosp = (const float*)d_in[2];
    const float* sinp = (const float*)d_in[3];
    const float* Wq = (const float*)d_in[4];
    const float* Wk = (const float*)d_in[5];
    const float* Wv = (const float*)d_in[6];
    const float* Wo = (const float*)d_in[7];
    float* out = (float*)d_out;

    float *q, *k, *v;
    bf16 *hid_i, *ctx_i, *wq_i, *wk_i, *wv_i, *wo_i;
    bf16 *qh, *ql, *kh, *kl, *vh, *vl;
    cudaGetSymbolAddress((void**)&q, g_q);
    cudaGetSymbolAddress((void**)&k, g_k);
    cudaGetSymbolAddress((void**)&v, g_v);
    cudaGetSymbolAddress((void**)&hid_i, g_hid_i);
    cudaGetSymbolAddress((void**)&ctx_i, g_ctx_i);
    cudaGetSymbolAddress((void**)&wq_i, g_wq_i);
    cudaGetSymbolAddress((void**)&wk_i, g_wk_i);
    cudaGetSymbolAddress((void**)&wv_i, g_wv_i);
    cudaGetSymbolAddress((void**)&wo_i, g_wo_i);
    cudaGetSymbolAddress((void**)&qh, g_qh);
    cudaGetSymbolAddress((void**)&ql, g_ql);
    cudaGetSymbolAddress((void**)&kh, g_kh);
    cudaGetSymbolAddress((void**)&kl, g_kl);
    cudaGetSymbolAddress((void**)&vh, g_vh);
    cudaGetSymbolAddress((void**)&vl, g_vl);

    const int M = B_ * T_;  // 4096

    cudaFuncSetAttribute(bf16gemm, cudaFuncAttributeMaxDynamicSharedMemorySize,
                         GSTAGES * (A_STAGE_BYTES + B_STAGE_BYTES));
    cudaFuncSetAttribute(flash_mma, cudaFuncAttributeMaxDynamicSharedMemorySize, 6 * FTILE);

    // GEMM input splits
    split_rows3<<<(M * HID_ + 255) / 256, 256>>>(hidden, hid_i, M * HID_);
    split_cols3<<<(HID_ * 2048 + 255) / 256, 256>>>(Wq, wq_i, HID_, 2048);
    split_cols3<<<(HID_ * 512 + 255) / 256, 256>>>(Wk, wk_i, HID_, 512);
    split_cols3<<<(HID_ * 512 + 255) / 256, 256>>>(Wv, wv_i, HID_, 512);
    split_cols3<<<(HID_ * 2048 + 255) / 256, 256>>>(Wo, wo_i, HID_, 2048);

    const int gsm = GSTAGES * (A_STAGE_BYTES + B_STAGE_BYTES);

    // projections
    bf16gemm<<<dim3(2048 / GBN, M / GBM), 256, gsm>>>(hid_i, wq_i, q, M, 2048, K3);
    bf16gemm<<<dim3(512 / GBN, M / GBM), 256, gsm>>>(hid_i, wk_i, k, M, 512, K3);
    bf16gemm<<<dim3(512 / GBN, M / GBM), 256, gsm>>>(hid_i, wv_i, v, M, 512, K3);

    // RoPE + split (q carries log2e/sqrt(HD) scale)
    const float qscale = 1.4426950408889634f * 0.08838834764831845f;
    rope_split<<<(B_ * T_ * NH_ * 64 + 255) / 256, 256>>>(q, cosp, sinp, qh, ql, NH_, qscale);
    rope_split<<<(B_ * T_ * KVH_ * 64 + 255) / 256, 256>>>(k, cosp, sinp, kh, kl, KVH_, 1.0f);
    split_hl<<<(M * KVH_ * HD_ + 255) / 256, 256>>>(v, vh, vl, M * KVH_ * HD_);

    // tensor-core flash attention -> triple-interleaved ctx
    flash_mma<<<dim3(T_ / 64, NH_, B_), 128, 6 * FTILE>>>(qh, ql, kh, kl, vh, vl, ctx_i);

    // output projection
    bf16gemm<<<dim3(2048 / GBN, M / GBM), 256, gsm>>>(ctx_i, wo_i, out, M, 2048, K3);
}